// round 13
// baseline (speedup 1.0000x reference)
#include <cuda_runtime.h>
#include <math.h>

// ---------------------------------------------------------------------------
// ROPE_64252710748794: out = 2 * 1.57 * sum_k sin(C(theta_k)) * vec[2k]
// (theta pairs bitwise equal => pair collapse).
// Rounds 5-12: DRAM pinned at ~5.2 TB/s (62-66%) across occupancy 41-92%,
// -40% instructions, cache policy, and reg-buffered MLP => every SM-side
// lever falsified. Round 13 tests the last untried path: cp.async.cg
// (LDGSTS) 3-stage smem pipeline — bytes in flight without registers or
// scoreboard slots, L1 bypass, full warp count. Per-thread-private slots
// (each thread reads only what it wrote) => no __syncthreads in the loop.
// est math identical to R12 (symmetry-folded discrete CORDIC, all-register).
// ---------------------------------------------------------------------------

#define TWO_PI_F   6.283185307179586f
#define PI_F       3.141592653589793f
#define PI_12_F    1.5707963267948966f
#define PI_14_F    0.7853981633974483f
#define INV2PI_F   0.15915494309189535f

#define D3_5_F     0.061086523819801536f
#define D8_13_F    0.14189526818745917f
#define D26_565_F  0.46364671567952505f
#define D16_26_F   0.28379053637491834f
#define D36_87_F   0.64350289521467380f

#define SIN_F1_F   0.27999656988459544f
#define COS_F1_F   0.96000100046478220f
#define SIN_F2_F   0.60000142963530880f
#define COS_F2_F   0.79999892777837827f
#define SIN_U_F    0.12403445401859652f
#define COS_U_F    0.99227790841661646f

#define STAGES      3
#define THREADS_CTA 256
#define STAGE_BYTES (THREADS_CTA * 16)

__device__ float        g_partials[4096];
__device__ unsigned int g_ticket;

__device__ __forceinline__ void cp16(unsigned dst_smem, const void* src_gmem) {
    asm volatile("cp.async.cg.shared.global [%0], [%1], 16;"
                 :: "r"(dst_smem), "l"(src_gmem));
}
#define CP_COMMIT() asm volatile("cp.async.commit_group;" ::: "memory")
#define CP_WAIT()   asm volatile("cp.async.wait_group %0;" :: "n"(STAGES - 1) : "memory")

// sin(C(theta)), C = the reference's discretely-applied CORDIC rotation.
// Symmetry-folded about pi/2 (Sterbenz-exact; classification unchanged).
__device__ __forceinline__ float est_sin(float theta) {
    float fn = rintf(theta * INV2PI_F);
    float t  = fmaf(-fn, TWO_PI_F, theta);

    float a  = fabsf(t);
    float ap = fminf(a, PI_F - a);        // [0, pi/2]

    bool  q1 = ap > PI_14_F;
    float r  = q1 ? (ap - PI_12_F) : ap;  // [-pi/4, pi/4]

    float ar    = fabsf(r);
    bool  f2    = ar >= D26_565_F;
    bool  f1    = ar >= D8_13_F;
    float Fv    = f2 ? D36_87_F : (f1 ? D16_26_F : 0.0f);
    float sinFs = copysignf(f2 ? SIN_F2_F : (f1 ? SIN_F1_F : 0.0f), r);
    float cosF  = f2 ? COS_F2_F : (f1 ? COS_F1_F : 1.0f);
    float r2    = r - copysignf(Fv, r);

    bool  um   = fabsf(r2) >= D3_5_F;
    float sinU = um ? copysignf(SIN_U_F, r2) : 0.0f;
    float cosU = um ? COS_U_F                : 1.0f;

    float sc = fmaf(sinFs, cosU,  cosF * sinU);
    float cc = fmaf(cosF,  cosU, -sinFs * sinU);

    float h = q1 ? cc : sc;               // h >= 0 in all regions
    return copysignf(h, t);
}

__global__ void __launch_bounds__(THREADS_CTA, 8) rope_dot_kernel(
    const float4* __restrict__ vec4,
    const float4* __restrict__ th4,
    const int*    __restrict__ m_ptr,
    float*        __restrict__ out,
    int n4)
{
    __shared__ float4 sv[STAGES][THREADS_CTA];
    __shared__ float4 st[STAGES][THREADS_CTA];

    const float m = (float)(*m_ptr);
    const int stride = gridDim.x * blockDim.x;   // 2^18: divides n4 = 2^22
    const int iters  = n4 / stride;              // 16
    const int tid    = threadIdx.x;
    const int i0     = blockIdx.x * blockDim.x + tid;

    const unsigned svb = (unsigned)__cvta_generic_to_shared(&sv[0][tid]);
    const unsigned stb = (unsigned)__cvta_generic_to_shared(&st[0][tid]);

    // prologue: fill STAGES-1 stages (one commit group per stage)
    #pragma unroll
    for (int s = 0; s < STAGES - 1; ++s) {
        int idx = i0 + s * stride;
        if (s < iters && idx < n4) {
            cp16(svb + s * STAGE_BYTES, vec4 + idx);
            cp16(stb + s * STAGE_BYTES, th4  + idx);
        }
        CP_COMMIT();
    }

    float acc0 = 0.0f, acc1 = 0.0f;
    #pragma unroll 3
    for (int it = 0; it < iters; ++it) {
        // issue stage it+STAGES-1 (empty commit keeps group numbering uniform)
        int isit = it + (STAGES - 1);
        if (isit < iters) {
            int idx = i0 + isit * stride;
            int sl  = isit % STAGES;
            cp16(svb + sl * STAGE_BYTES, vec4 + idx);
            cp16(stb + sl * STAGE_BYTES, th4  + idx);
        }
        CP_COMMIT();
        CP_WAIT();                                 // stage `it` resident

        int sl = it % STAGES;
        float4 v = sv[sl][tid];                    // private slot: no barrier
        float4 t = st[sl][tid];
        acc0 = fmaf(est_sin(m * t.x), v.x, acc0);
        acc1 = fmaf(est_sin(m * t.z), v.z, acc1);
    }

    // generic tail (empty for this shape; keeps kernel shape-robust)
    for (int j = i0 + iters * stride; j < n4; j += stride) {
        float4 vt = __ldg(&vec4[j]);
        float4 tt = __ldg(&th4[j]);
        acc0 = fmaf(est_sin(m * tt.x), vt.x, acc0);
        acc1 = fmaf(est_sin(m * tt.z), vt.z, acc1);
    }
    float acc = acc0 + acc1;

    #pragma unroll
    for (int off = 16; off > 0; off >>= 1)
        acc += __shfl_down_sync(0xffffffffu, acc, off);

    __shared__ float sh[8];
    __shared__ bool  is_last;
    int lane = threadIdx.x & 31;
    int w    = threadIdx.x >> 5;
    if (lane == 0) sh[w] = acc;
    __syncthreads();
    if (threadIdx.x == 0) {
        float b = sh[0];
        #pragma unroll
        for (int k = 1; k < 8; k++) b += sh[k];
        g_partials[blockIdx.x] = b;
        __threadfence();
        unsigned tk = atomicAdd(&g_ticket, 1u);
        is_last = (tk == gridDim.x - 1);
    }
    __syncthreads();

    if (is_last) {
        double a = 0.0;
        for (int k = threadIdx.x; k < gridDim.x; k += blockDim.x)
            a += (double)g_partials[k];
        #pragma unroll
        for (int off = 16; off > 0; off >>= 1)
            a += __shfl_down_sync(0xffffffffu, a, off);
        __shared__ double shd[8];
        if (lane == 0) shd[w] = a;
        __syncthreads();
        if (threadIdx.x == 0) {
            double tot = shd[0];
            #pragma unroll
            for (int k = 1; k < 8; k++) tot += shd[k];
            out[0] = (float)(tot * (2.0 * (double)1.57f));
            g_ticket = 0;   // reset for next graph replay
        }
    }
}

extern "C" void kernel_launch(void* const* d_in, const int* in_sizes, int n_in,
                              void* d_out, int out_size) {
    const float4* vec4 = (const float4*)d_in[0];
    const float4* th4  = (const float4*)d_in[1];
    const int*    mptr = (const int*)d_in[2];

    int n  = in_sizes[0];
    int n4 = n / 4;

    const int threads = THREADS_CTA;
    const int blocks  = 1024;  // 2^18 threads: n4/threads = 16 exact iters

    rope_dot_kernel<<<blocks, threads>>>(vec4, th4, mptr, (float*)d_out, n4);
}

// round 14
// speedup vs baseline: 1.0811x; 1.0811x over previous
#include <cuda_runtime.h>
#include <math.h>

// ---------------------------------------------------------------------------
// ROPE_64252710748794: out = 2 * 1.57 * sum_k sin(C(theta_k)) * vec[2k]
// (theta pairs bitwise equal => pair collapse).
// est entirely in registers, symmetry-folded discrete CORDIC (R12).
// Rounds 5-13 falsified: occupancy, instruction count, reg-MLP, cache policy,
// cp.async path — DRAM pinned ~5.2 TB/s. Round 14 tests the last untouched
// dimension: DRAM row locality. Block-contiguous tiling (each block owns a
// contiguous 64 KB chunk per array; threads stride 256 within it) keeps
// per-warp coalescing identical but makes consecutive iterations touch
// adjacent rows instead of 4 MB apart.
// ---------------------------------------------------------------------------

#define TWO_PI_F   6.283185307179586f
#define PI_F       3.141592653589793f
#define PI_12_F    1.5707963267948966f
#define PI_14_F    0.7853981633974483f
#define INV2PI_F   0.15915494309189535f

#define D3_5_F     0.061086523819801536f
#define D8_13_F    0.14189526818745917f
#define D26_565_F  0.46364671567952505f
#define D16_26_F   0.28379053637491834f
#define D36_87_F   0.64350289521467380f

#define SIN_F1_F   0.27999656988459544f
#define COS_F1_F   0.96000100046478220f
#define SIN_F2_F   0.60000142963530880f
#define COS_F2_F   0.79999892777837827f
#define SIN_U_F    0.12403445401859652f
#define COS_U_F    0.99227790841661646f

__device__ float        g_partials[4096];
__device__ unsigned int g_ticket;

// sin(C(theta)), C = the reference's discretely-applied CORDIC rotation.
// Symmetry-folded about pi/2 (Sterbenz-exact; classification unchanged).
__device__ __forceinline__ float est_sin(float theta) {
    float fn = rintf(theta * INV2PI_F);
    float t  = fmaf(-fn, TWO_PI_F, theta);

    float a  = fabsf(t);
    float ap = fminf(a, PI_F - a);        // [0, pi/2]

    bool  q1 = ap > PI_14_F;
    float r  = q1 ? (ap - PI_12_F) : ap;  // [-pi/4, pi/4]

    float ar    = fabsf(r);
    bool  f2    = ar >= D26_565_F;
    bool  f1    = ar >= D8_13_F;
    float Fv    = f2 ? D36_87_F : (f1 ? D16_26_F : 0.0f);
    float sinFs = copysignf(f2 ? SIN_F2_F : (f1 ? SIN_F1_F : 0.0f), r);
    float cosF  = f2 ? COS_F2_F : (f1 ? COS_F1_F : 1.0f);
    float r2    = r - copysignf(Fv, r);

    bool  um   = fabsf(r2) >= D3_5_F;
    float sinU = um ? copysignf(SIN_U_F, r2) : 0.0f;
    float cosU = um ? COS_U_F                : 1.0f;

    float sc = fmaf(sinFs, cosU,  cosF * sinU);
    float cc = fmaf(cosF,  cosU, -sinFs * sinU);

    float h = q1 ? cc : sc;               // h >= 0 in all regions
    return copysignf(h, t);
}

__global__ void __launch_bounds__(256, 7) rope_dot_kernel(
    const float4* __restrict__ vec4,
    const float4* __restrict__ th4,
    const int*    __restrict__ m_ptr,
    float*        __restrict__ out,
    int n4)
{
    const float m = (float)(*m_ptr);
    // block-contiguous tiling: block owns [blockIdx*chunk, (blockIdx+1)*chunk)
    const int chunk = n4 / gridDim.x;            // 4096 float4 (exact: 2^22/2^10)
    const int base  = blockIdx.x * chunk;
    const int iters = chunk / blockDim.x;        // 16 (exact)
    float acc0 = 0.0f, acc1 = 0.0f;

    int i = base + threadIdx.x;
    float4 v = __ldg(&vec4[i]);
    float4 t = __ldg(&th4[i]);

    // steady state: unconditional next-tile loads, double-buffered;
    // consecutive iterations touch adjacent 4 KB (row locality)
    for (int it = 1; it < iters; ++it) {
        int j = i + blockDim.x;
        float4 vn = __ldg(&vec4[j]);
        float4 tn = __ldg(&th4[j]);
        acc0 = fmaf(est_sin(m * t.x), v.x, acc0);
        acc1 = fmaf(est_sin(m * t.z), v.z, acc1);
        v = vn; t = tn; i = j;
    }
    acc0 = fmaf(est_sin(m * t.x), v.x, acc0);
    acc1 = fmaf(est_sin(m * t.z), v.z, acc1);

    // generic tail: cover any remainder of this block's chunk, plus (last
    // block only) any global remainder beyond gridDim*chunk. Empty here.
    int done = base + iters * (int)blockDim.x;
    int lim  = (blockIdx.x == gridDim.x - 1) ? n4 : (base + chunk);
    for (int j = done + (int)threadIdx.x; j < lim; j += blockDim.x) {
        float4 vt = __ldg(&vec4[j]);
        float4 tt = __ldg(&th4[j]);
        acc0 = fmaf(est_sin(m * tt.x), vt.x, acc0);
        acc1 = fmaf(est_sin(m * tt.z), vt.z, acc1);
    }
    float acc = acc0 + acc1;

    #pragma unroll
    for (int off = 16; off > 0; off >>= 1)
        acc += __shfl_down_sync(0xffffffffu, acc, off);

    __shared__ float sh[8];
    __shared__ bool  is_last;
    int lane = threadIdx.x & 31;
    int w    = threadIdx.x >> 5;
    if (lane == 0) sh[w] = acc;
    __syncthreads();
    if (threadIdx.x == 0) {
        float b = sh[0];
        #pragma unroll
        for (int k = 1; k < 8; k++) b += sh[k];
        g_partials[blockIdx.x] = b;
        __threadfence();
        unsigned tk = atomicAdd(&g_ticket, 1u);
        is_last = (tk == gridDim.x - 1);
    }
    __syncthreads();

    if (is_last) {
        double a = 0.0;
        for (int k = threadIdx.x; k < gridDim.x; k += blockDim.x)
            a += (double)g_partials[k];
        #pragma unroll
        for (int off = 16; off > 0; off >>= 1)
            a += __shfl_down_sync(0xffffffffu, a, off);
        __shared__ double shd[8];
        if (lane == 0) shd[w] = a;
        __syncthreads();
        if (threadIdx.x == 0) {
            double tot = shd[0];
            #pragma unroll
            for (int k = 1; k < 8; k++) tot += shd[k];
            out[0] = (float)(tot * (2.0 * (double)1.57f));
            g_ticket = 0;   // reset for next graph replay
        }
    }
}

extern "C" void kernel_launch(void* const* d_in, const int* in_sizes, int n_in,
                              void* d_out, int out_size) {
    const float4* vec4 = (const float4*)d_in[0];
    const float4* th4  = (const float4*)d_in[1];
    const int*    mptr = (const int*)d_in[2];

    int n  = in_sizes[0];
    int n4 = n / 4;

    const int threads = 256;
    const int blocks  = 1024;  // chunk = 4096 float4 = 64 KB/array per block

    rope_dot_kernel<<<blocks, threads>>>(vec4, th4, mptr, (float*)d_out, n4);
}